// round 10
// baseline (speedup 1.0000x reference)
#include <cuda_runtime.h>
#include <math.h>

#define S 32768

static __device__ float g_qkvt[2*192*S];
static __device__ float g_nrm[2*128];
static __device__ float g_Gpart[2*4*16*256];
static __device__ float g_attn[2*4*256];
static __device__ float g_x5[2*64*S];
static __device__ float g_u[2*64*S];
static __device__ float g_a1[2*64*S];
static __device__ float g_a2[2*64*S];
static __device__ float g_off[2*81*S];
static __device__ float g_dcn[2*64*S];
static __device__ float g_yfin[2*64*S];
static __device__ float g_offw_t[27*96*64];   // padded to 96 output slots
static __device__ float g_dcnw_t[27*64*64];

__device__ __forceinline__ float* bufptr(int id){
  switch(id){case 0:return g_x5;case 1:return g_u;case 2:return g_a1;
  case 3:return g_a2;case 4:return g_dcn;default:return g_yfin;}
}

__global__ void k_wprep(const float* __restrict__ offw,const float* __restrict__ dcnw){
  int t=blockIdx.x*256+threadIdx.x;
  if(t<27*96*64){int k=t/(96*64);int rem=t-k*96*64;int o=rem>>6,c=rem&63;
    g_offw_t[t]=(o<81)?offw[(o*64+c)*27+k]:0.f;}
  if(t<27*64*64){int k=t>>12;int rem=t&4095;int o=rem>>6,c=rem&63;
    g_dcnw_t[t]=dcnw[(o*64+c)*27+k];}
}

__global__ __launch_bounds__(256) void k_qkv(const float* __restrict__ x,const float* __restrict__ w){
  __shared__ float xs[64][65],ws[64][65];
  int b=blockIdx.x>>9,n0=(blockIdx.x&511)<<6,t=threadIdx.x;
  const float* xp=x+(b*S+n0)*64;
  for(int i=0;i<16;i++){int e=t+256*i;xs[e>>6][e&63]=xp[e];}
  int ng=t&15,og=t>>4;
  for(int pass=0;pass<3;pass++){
    __syncthreads();
    for(int i=0;i<16;i++){int e=t+256*i;ws[e>>6][e&63]=w[pass*4096+e];}
    __syncthreads();
    float acc[4][4];
    for(int i=0;i<4;i++)for(int m=0;m<4;m++)acc[i][m]=0.f;
    for(int c=0;c<64;c++){
      float xv[4],wv[4];
      #pragma unroll
      for(int m=0;m<4;m++)xv[m]=xs[ng+16*m][c];
      #pragma unroll
      for(int i=0;i<4;i++)wv[i]=ws[og+16*i][c];
      #pragma unroll
      for(int i=0;i<4;i++)
        #pragma unroll
        for(int m=0;m<4;m++)acc[i][m]+=wv[i]*xv[m];
    }
    for(int i=0;i<4;i++){int j=pass*64+og+16*i;
      for(int m=0;m<4;m++)g_qkvt[(b*192+j)*S+n0+ng+16*m]=acc[i][m];}
  }
}

__global__ void k_sumsq(){
  int b=blockIdx.x>>7,j=blockIdx.x&127,t=threadIdx.x;
  const float* row=g_qkvt+(b*192+j)*S;
  float p=0.f;
  for(int i=0;i<128;i++){float v=row[t+256*i];p+=v*v;}
  __shared__ float red[256];
  red[t]=p;__syncthreads();
  for(int st=128;st>0;st>>=1){if(t<st)red[t]+=red[t+st];__syncthreads();}
  if(t==0)g_nrm[b*128+j]=fmaxf(sqrtf(red[0]),1e-12f);
}

__global__ __launch_bounds__(256) void k_gram(){
  __shared__ float qs[16][129],ks[16][129];
  int id=blockIdx.x,chunk=id&15,h=(id>>4)&3,b=id>>6,t=threadIdx.x;
  int c=t>>4,d=t&15,nbase=chunk*2048;
  const float* qrow=g_qkvt+(b*192+h*16)*S;
  const float* krow=g_qkvt+(b*192+64+h*16)*S;
  float acc=0.f;
  for(int ch=0;ch<16;ch++){
    int nb=nbase+ch*128;
    __syncthreads();
    for(int i=0;i<16;i++){int e=t+256*i;int r=e>>7,n=e&127;
      if(r<16)qs[r][n]=qrow[r*S+nb+n];else ks[r-16][n]=krow[(r-16)*S+nb+n];}
    __syncthreads();
    for(int n=0;n<128;n++)acc+=qs[c][n]*ks[d][n];
  }
  g_Gpart[((b*4+h)*16+chunk)*256+c*16+d]=acc;
}

__global__ void k_softmax(const float* __restrict__ temp){
  int b=blockIdx.x>>2,h=blockIdx.x&3,t=threadIdx.x;
  int c=t>>4,d=t&15;
  float g=0.f;
  for(int ch=0;ch<16;ch++)g+=g_Gpart[((b*4+h)*16+ch)*256+t];
  float nq=g_nrm[b*128+h*16+c],nk=g_nrm[b*128+64+h*16+d];
  float v=g/(nq*nk)*temp[h];
  float m=v;
  for(int o=8;o;o>>=1)m=fmaxf(m,__shfl_xor_sync(0xffffffffu,m,o,16));
  float e=expf(v-m),s2=e;
  for(int o=8;o;o>>=1)s2+=__shfl_xor_sync(0xffffffffu,s2,o,16);
  g_attn[(b*4+h)*256+c*16+d]=e/s2;
}

__global__ __launch_bounds__(256) void k_xca(const float* __restrict__ nw,const float* __restrict__ nb){
  __shared__ float vs[64][65],xc[64][65],at[1024],mu[64],rs[64];
  int b=blockIdx.x>>9,n0=(blockIdx.x&511)<<6,t=threadIdx.x;
  for(int i=0;i<16;i++){int e=t+256*i;int r=e>>6,n=e&63;
    vs[r][n]=g_qkvt[(b*192+128+r)*S+n0+n];}
  for(int i=0;i<4;i++)at[t+256*i]=g_attn[b*1024+t+256*i];
  __syncthreads();
  int sl=t&63,og=t>>6;
  for(int i=0;i<16;i++){
    float a=0.f;
    const float* ar=at+og*256+i*16;
    #pragma unroll
    for(int d=0;d<16;d++)a+=ar[d]*vs[og*16+d][sl];
    xc[og*16+i][sl]=a;
  }
  __syncthreads();
  if(t<64){
    float s1=0.f;
    for(int c2=0;c2<64;c2++)s1+=xc[c2][t];
    float m=s1*(1.f/64.f),sq=0.f;
    for(int c2=0;c2<64;c2++){float d2=xc[c2][t]-m;sq+=d2*d2;}
    mu[t]=m;rs[t]=rsqrtf(sq*(1.f/64.f)+1e-5f);
  }
  __syncthreads();
  for(int i=0;i<16;i++){int c=og*16+i;
    g_x5[(b*64+c)*S+n0+sl]=(xc[c][sl]-mu[sl])*rs[sl]*nw[c]+nb[c];}
}

template<int MODE>
__global__ __launch_bounds__(256) void k_pw(int inid,int auxid,int outid,
    const float* __restrict__ w,const float* __restrict__ bias){
  __shared__ float xs[64][65],ws2[64][65];
  const float* in=bufptr(inid);const float* aux=bufptr(auxid);float* out=bufptr(outid);
  int b=blockIdx.x>>9,s0=(blockIdx.x&511)<<6,t=threadIdx.x;
  for(int i=0;i<16;i++){int e=t+256*i;int c=e>>6,s=e&63;
    xs[c][s]=in[(b*64+c)*S+s0+s];ws2[c][s]=w[e];}
  __syncthreads();
  int sg=t&15,og=t>>4;
  float acc[4][4];
  for(int i=0;i<4;i++)for(int m=0;m<4;m++)acc[i][m]=0.f;
  for(int c=0;c<64;c++){
    float xv[4],wv[4];
    #pragma unroll
    for(int m=0;m<4;m++)xv[m]=xs[c][sg+16*m];
    #pragma unroll
    for(int i=0;i<4;i++)wv[i]=ws2[og+16*i][c];
    #pragma unroll
    for(int i=0;i<4;i++)
      #pragma unroll
      for(int m=0;m<4;m++)acc[i][m]+=wv[i]*xv[m];
  }
  for(int i=0;i<4;i++){
    int o=og+16*i;float bv=bias[o];
    for(int m=0;m<4;m++){
      int idx=(b*64+o)*S+s0+sg+16*m;
      float v=acc[i][m]+bv;
      if(MODE==1)v=0.5f*v*(1.f+erff(v*0.70710678118654752f));
      if(MODE==2)v*=aux[idx];
      if(MODE==3)v+=aux[idx];
      out[idx]=v;
    }
  }
}

__global__ __launch_bounds__(256) void k_dw5(int inid,int outid,
    const float* __restrict__ wt,const float* __restrict__ bias){
  __shared__ float pl[5][32][33];__shared__ float wsm[125];
  const float* in=bufptr(inid);float* out=bufptr(outid);
  int bc=blockIdx.x>>5,z=blockIdx.x&31,c=bc&63,t=threadIdx.x;
  if(t<125)wsm[t]=wt[c*125+t];
  const float* base=in+bc*S;
  for(int i=0;i<20;i++){int e=t+256*i;int p=e>>10,rem=e&1023;
    int zz=z+p-2;pl[p][rem>>5][rem&31]=((unsigned)zz<32u)?base[zz*1024+rem]:0.f;}
  __syncthreads();
  int x=t&31,ty=t>>5;
  for(int m=0;m<4;m++){
    int y=ty+8*m;float a=bias[c];
    for(int tz=0;tz<5;tz++)for(int qy=0;qy<5;qy++){
      int yy=y+qy-2;
      if((unsigned)yy<32u)
        #pragma unroll
        for(int qx=0;qx<5;qx++){int xx=x+qx-2;
          if((unsigned)xx<32u)a+=wsm[(tz*5+qy)*5+qx]*pl[tz][yy][xx];}
    }
    out[bc*S+z*1024+y*32+x]=a;
  }
}

__global__ __launch_bounds__(256) void k_dw7(int inid,int outid,
    const float* __restrict__ wt,const float* __restrict__ bias){
  __shared__ float pl[7][32][33];__shared__ float wsm[343];
  const float* in=bufptr(inid);float* out=bufptr(outid);
  int bc=blockIdx.x>>5,z=blockIdx.x&31,c=bc&63,t=threadIdx.x;
  for(int i=t;i<343;i+=256)wsm[i]=wt[c*343+i];
  const float* base=in+bc*S;
  for(int i=0;i<28;i++){int e=t+256*i;int p=e>>10,rem=e&1023;
    int zz=z+3*p-9;pl[p][rem>>5][rem&31]=((unsigned)zz<32u)?base[zz*1024+rem]:0.f;}
  __syncthreads();
  int x=t&31,ty=t>>5;
  for(int m=0;m<4;m++){
    int y=ty+8*m;float a=bias[c];
    for(int tz=0;tz<7;tz++)for(int qy=0;qy<7;qy++){
      int yy=y+3*qy-9;
      if((unsigned)yy<32u)
        #pragma unroll
        for(int qx=0;qx<7;qx++){int xx=x+3*qx-9;
          if((unsigned)xx<32u)a+=wsm[(tz*7+qy)*7+qx]*pl[tz][yy][xx];}
    }
    out[bc*S+z*1024+y*32+x]=a;
  }
}

__global__ __launch_bounds__(256) void k_off(const float* __restrict__ offb){
  __shared__ float rows[2][64][34];__shared__ float wsm[96*64];
  int blk=blockIdx.x;
  int b=blk>>9,z=(blk>>4)&31,y0=(blk&15)<<1,t=threadIdx.x;
  int xg=t&15,og=t>>4;
  float acc[2][2][6];
  for(int r=0;r<2;r++)for(int m=0;m<2;m++)for(int j=0;j<6;j++)acc[r][m][j]=0.f;
  const float* ab=g_a2+b*64*S;
  for(int tz=0;tz<3;tz++){
    int zz=z+tz-1;bool zok=(unsigned)zz<32u;
    for(int ty=0;ty<3;ty++){
      __syncthreads();
      for(int i=0;i<17;i++){
        int e=t+256*i;int r=e/2176,rem=e-r*2176;
        int cc=rem/34,xi=rem-cc*34;
        int yy=y0+ty-1+r,gx=xi-1;
        float v=0.f;
        if(zok&&(unsigned)yy<32u&&(unsigned)gx<32u)v=ab[cc*S+zz*1024+yy*32+gx];
        rows[r][cc][xi]=v;
      }
      for(int tx=0;tx<3;tx++){
        int k=(tz*3+ty)*3+tx;
        __syncthreads();
        for(int i=0;i<24;i++){int e=t+256*i;wsm[e]=g_offw_t[k*6144+e];}
        __syncthreads();
        for(int cc=0;cc<64;cc++){
          float xv[2][2];
          #pragma unroll
          for(int r=0;r<2;r++)
            #pragma unroll
            for(int m=0;m<2;m++)xv[r][m]=rows[r][cc][xg+16*m+tx];
          #pragma unroll
          for(int j=0;j<6;j++){
            float wv=wsm[(og*6+j)*64+cc];
            #pragma unroll
            for(int r=0;r<2;r++)
              #pragma unroll
              for(int m=0;m<2;m++)acc[r][m][j]+=wv*xv[r][m];
          }
        }
      }
    }
  }
  for(int j=0;j<6;j++){
    int o=og*6+j;
    if(o<81){
      float bv=offb[o];
      for(int r=0;r<2;r++)for(int m=0;m<2;m++){
        int s=z*1024+(y0+r)*32+xg+16*m;
        g_off[(b*81+o)*S+s]=acc[r][m][j]+bv;
      }
    }
  }
}

__global__ __launch_bounds__(256) void k_dcn(const float* __restrict__ dcnb){
  extern __shared__ float dyn[];
  float* samp=dyn;            // 64*128
  float* wsm=dyn+8192;        // 4096
  float* cw=wsm+4096;         // 8*128
  int* ci=(int*)(cw+1024);    // 8*128
  int b=blockIdx.x>>8,s0=(blockIdx.x&255)<<7,t=threadIdx.x;
  int sl=t&31,og=t>>5;
  float acc[4][8];
  for(int m=0;m<4;m++)for(int i=0;i<8;i++)acc[m][i]=0.f;
  const float* ab=g_a2+b*64*S;
  for(int k=0;k<27;k++){
    __syncthreads();
    if(t<128){
      int s=s0+t;
      int z=s>>10,y=(s>>5)&31,x=s&31;
      int kz=k/9,ky=(k/3)%3,kx=k%3;
      float pz=(float)(z+kz-1)+g_off[(b*81+3*k+0)*S+s];
      float py=(float)(y+ky-1)+g_off[(b*81+3*k+1)*S+s];
      float px=(float)(x+kx-1)+g_off[(b*81+3*k+2)*S+s];
      float fz=floorf(pz),fy=floorf(py),fx=floorf(px);
      float wz=pz-fz,wy=py-fy,wx=px-fx;
      int z0=(int)fz,y0=(int)fy,x0=(int)fx;
      #pragma unroll
      for(int cn=0;cn<8;cn++){
        int dz=cn>>2,dy=(cn>>1)&1,dx=cn&1;
        int iz=z0+dz,iy=y0+dy,ix=x0+dx;
        float wv=(dz?wz:1.f-wz)*(dy?wy:1.f-wy)*(dx?wx:1.f-wx);
        bool ok=(unsigned)iz<32u&&(unsigned)iy<32u&&(unsigned)ix<32u;
        int czi=min(max(iz,0),31),cyi=min(max(iy,0),31),cxi=min(max(ix,0),31);
        cw[cn*128+t]=ok?wv:0.f;
        ci[cn*128+t]=(czi*32+cyi)*32+cxi;
      }
    }
    for(int i=0;i<16;i++)wsm[t+256*i]=g_dcnw_t[k*4096+t+256*i];
    __syncthreads();
    for(int i=0;i<32;i++){
      int e=t+256*i;int cc=e>>7,sp=e&127;
      const float* ap=ab+cc*S;
      float v=0.f;
      #pragma unroll
      for(int cn=0;cn<8;cn++)v+=cw[cn*128+sp]*ap[ci[cn*128+sp]];
      samp[cc*128+sp]=v;
    }
    __syncthreads();
    for(int cc=0;cc<64;cc++){
      float xv[4];
      #pragma unroll
      for(int m=0;m<4;m++)xv[m]=samp[cc*128+sl+32*m];
      #pragma unroll
      for(int i=0;i<8;i++){
        float wv=wsm[(og+8*i)*64+cc];
        #pragma unroll
        for(int m=0;m<4;m++)acc[m][i]+=wv*xv[m];
      }
    }
  }
  for(int i=0;i<8;i++){
    int o=og+8*i;float bv=dcnb[o];
    for(int m=0;m<4;m++)
      g_dcn[(b*64+o)*S+s0+sl+32*m]=acc[m][i]+bv;
  }
}

__global__ __launch_bounds__(256) void k_final(const float* __restrict__ n2w,
    const float* __restrict__ n2b,const float* __restrict__ ow,
    const float* __restrict__ ob,float* __restrict__ out){
  __shared__ float Msm[64][65],wsm[64][65],mu[64],rs[64];
  int b=blockIdx.x>>9,g=blockIdx.x&511,t=threadIdx.x;
  for(int i=0;i<16;i++){int e=t+256*i;int r=e>>6,p=e&63;
    Msm[r][p]=g_yfin[(b*64+r)*S+g+(p<<9)];
    wsm[r][p]=ow[e];}
  __syncthreads();
  if(t<64){
    float s1=0.f;
    for(int p=0;p<64;p++)s1+=Msm[t][p];
    float m=s1*(1.f/64.f),sq=0.f;
    for(int p=0;p<64;p++){float d=Msm[t][p]-m;sq+=d*d;}
    mu[t]=m;rs[t]=rsqrtf(sq*(1.f/64.f)+1e-5f);
  }
  __syncthreads();
  for(int i=0;i<16;i++){int e=t+256*i;int r=e>>6,p=e&63;
    Msm[r][p]=(Msm[r][p]-mu[r])*rs[r]*n2w[p]+n2b[p];}
  __syncthreads();
  int og=t&15,sg=t>>4;
  float acc[4][4];
  for(int m=0;m<4;m++)for(int i=0;i<4;i++)acc[m][i]=0.f;
  for(int p=0;p<64;p++){
    float xv[4],wv[4];
    #pragma unroll
    for(int m=0;m<4;m++)xv[m]=Msm[sg+16*m][p];
    #pragma unroll
    for(int i=0;i<4;i++)wv[i]=wsm[og+16*i][p];
    #pragma unroll
    for(int m=0;m<4;m++)
      #pragma unroll
      for(int i=0;i<4;i++)acc[m][i]+=xv[m]*wv[i];
  }
  for(int m=0;m<4;m++){
    int q=(g<<6)+sg+16*m;
    for(int i=0;i<4;i++){
      int o=og+16*i;
      out[(b*S+q)*64+o]=acc[m][i]+ob[o];
    }
  }
}

extern "C" void kernel_launch(void* const* d_in,const int* in_sizes,int n_in,
                              void* d_out,int out_size){
  const float* x   =(const float*)d_in[0];
  const float* temp=(const float*)d_in[1];
  const float* qkvw=(const float*)d_in[2];
  const float* nw  =(const float*)d_in[3];
  const float* nb  =(const float*)d_in[4];
  const float* p1w =(const float*)d_in[5];
  const float* p1b =(const float*)d_in[6];
  const float* c0w =(const float*)d_in[7];
  const float* c0b =(const float*)d_in[8];
  const float* cspw=(const float*)d_in[9];
  const float* cspb=(const float*)d_in[10];
  const float* offw=(const float*)d_in[11];
  const float* offb=(const float*)d_in[12];
  const float* dcnw=(const float*)d_in[13];
  const float* dcnb=(const float*)d_in[14];
  const float* c1w =(const float*)d_in[15];
  const float* c1b =(const float*)d_in[16];
  const float* p2w =(const float*)d_in[17];
  const float* p2b =(const float*)d_in[18];
  const float* n2w =(const float*)d_in[19];
  const float* n2b =(const float*)d_in[20];
  const float* ow  =(const float*)d_in[21];
  const float* ob  =(const float*)d_in[22];
  float* out=(float*)d_out;

  cudaFuncSetAttribute(k_dcn,cudaFuncAttributeMaxDynamicSharedMemorySize,57344);

  k_wprep<<<648,256>>>(offw,dcnw);
  k_qkv<<<1024,256>>>(x,qkvw);
  k_sumsq<<<256,256>>>();
  k_gram<<<128,256>>>();
  k_softmax<<<8,256>>>(temp);
  k_xca<<<1024,256>>>(nw,nb);
  k_pw<1><<<1024,256>>>(0,0,1,p1w,p1b);   // u = gelu(proj1(x5))
  k_dw5<<<4096,256>>>(1,2,c0w,c0b);       // a1 = dw5(u)
  k_dw7<<<4096,256>>>(2,3,cspw,cspb);     // a2 = dw7(a1)
  k_off<<<1024,256>>>(offb);              // offsets from a2
  k_dcn<<<512,256,57344>>>(dcnb);         // deformable conv
  k_pw<2><<<1024,256>>>(4,1,2,c1w,c1b);   // a1 = (conv1(dcn)+b)*u
  k_pw<3><<<1024,256>>>(2,0,5,p2w,p2b);   // yfin = proj2(a1)+x5
  k_final<<<1024,256>>>(n2w,n2b,ow,ob,out);
}

// round 11
// speedup vs baseline: 1.0657x; 1.0657x over previous
#include <cuda_runtime.h>
#include <math.h>

#define S 32768

static __device__ float g_qkvt[2*192*S];
static __device__ float g_nrm[2*128];
static __device__ float g_Gpart[2*4*16*256];
static __device__ float g_attn[2*4*256];
static __device__ float g_x5[2*64*S];
static __device__ float g_u[2*64*S];
static __device__ float g_a1[2*64*S];
static __device__ float g_a2[2*64*S];
static __device__ float g_off[2*81*S];
static __device__ float g_dcn[2*64*S];
static __device__ float g_yfin[2*64*S];
static __device__ float g_offw_t[27*96*64];   // [tap][o pad96][c]
static __device__ float g_dcnw_t[27*64*64];   // [tap][o][c]

__device__ __forceinline__ float* bufptr(int id){
  switch(id){case 0:return g_x5;case 1:return g_u;case 2:return g_a1;
  case 3:return g_a2;case 4:return g_dcn;default:return g_yfin;}
}

__device__ __forceinline__ float tf32r(float x){
  unsigned u; asm("cvt.rna.tf32.f32 %0,%1;":"=r"(u):"f"(x));
  return __uint_as_float(u);
}

__device__ __forceinline__ void mma8(float* d,const unsigned* a,unsigned b0,unsigned b1){
  asm volatile("mma.sync.aligned.m16n8k8.row.col.f32.tf32.tf32.f32 "
    "{%0,%1,%2,%3},{%4,%5,%6,%7},{%8,%9},{%0,%1,%2,%3};"
    :"+f"(d[0]),"+f"(d[1]),"+f"(d[2]),"+f"(d[3])
    :"r"(a[0]),"r"(a[1]),"r"(a[2]),"r"(a[3]),"r"(b0),"r"(b1));
}

__global__ void k_wprep(const float* __restrict__ offw,const float* __restrict__ dcnw){
  int t=blockIdx.x*256+threadIdx.x;
  if(t<27*96*64){int k=t/(96*64);int rem=t-k*96*64;int o=rem>>6,c=rem&63;
    g_offw_t[t]=(o<81)?offw[(o*64+c)*27+k]:0.f;}
  if(t<27*64*64){int k=t>>12;int rem=t&4095;int o=rem>>6,c=rem&63;
    g_dcnw_t[t]=dcnw[(o*64+c)*27+k];}
}

__global__ __launch_bounds__(256) void k_qkv(const float* __restrict__ x,const float* __restrict__ w){
  __shared__ float xs[64][65],ws[64][65];
  int b=blockIdx.x>>9,n0=(blockIdx.x&511)<<6,t=threadIdx.x;
  const float* xp=x+(b*S+n0)*64;
  for(int i=0;i<16;i++){int e=t+256*i;xs[e>>6][e&63]=xp[e];}
  int ng=t&15,og=t>>4;
  for(int pass=0;pass<3;pass++){
    __syncthreads();
    for(int i=0;i<16;i++){int e=t+256*i;ws[e>>6][e&63]=w[pass*4096+e];}
    __syncthreads();
    float acc[4][4];
    for(int i=0;i<4;i++)for(int m=0;m<4;m++)acc[i][m]=0.f;
    for(int c=0;c<64;c++){
      float xv[4],wv[4];
      #pragma unroll
      for(int m=0;m<4;m++)xv[m]=xs[ng+16*m][c];
      #pragma unroll
      for(int i=0;i<4;i++)wv[i]=ws[og+16*i][c];
      #pragma unroll
      for(int i=0;i<4;i++)
        #pragma unroll
        for(int m=0;m<4;m++)acc[i][m]+=wv[i]*xv[m];
    }
    for(int i=0;i<4;i++){int j=pass*64+og+16*i;
      for(int m=0;m<4;m++)g_qkvt[(b*192+j)*S+n0+ng+16*m]=acc[i][m];}
  }
}

__global__ void k_sumsq(){
  int b=blockIdx.x>>7,j=blockIdx.x&127,t=threadIdx.x;
  const float* row=g_qkvt+(b*192+j)*S;
  float p=0.f;
  for(int i=0;i<128;i++){float v=row[t+256*i];p+=v*v;}
  __shared__ float red[256];
  red[t]=p;__syncthreads();
  for(int st=128;st>0;st>>=1){if(t<st)red[t]+=red[t+st];__syncthreads();}
  if(t==0)g_nrm[b*128+j]=fmaxf(sqrtf(red[0]),1e-12f);
}

__global__ __launch_bounds__(256) void k_gram(){
  __shared__ float qs[16][129],ks[16][129];
  int id=blockIdx.x,chunk=id&15,h=(id>>4)&3,b=id>>6,t=threadIdx.x;
  int c=t>>4,d=t&15,nbase=chunk*2048;
  const float* qrow=g_qkvt+(b*192+h*16)*S;
  const float* krow=g_qkvt+(b*192+64+h*16)*S;
  float acc=0.f;
  for(int ch=0;ch<16;ch++){
    int nb=nbase+ch*128;
    __syncthreads();
    for(int i=0;i<16;i++){int e=t+256*i;int r=e>>7,n=e&127;
      if(r<16)qs[r][n]=qrow[r*S+nb+n];else ks[r-16][n]=krow[(r-16)*S+nb+n];}
    __syncthreads();
    for(int n=0;n<128;n++)acc+=qs[c][n]*ks[d][n];
  }
  g_Gpart[((b*4+h)*16+chunk)*256+c*16+d]=acc;
}

__global__ void k_softmax(const float* __restrict__ temp){
  int b=blockIdx.x>>2,h=blockIdx.x&3,t=threadIdx.x;
  int c=t>>4,d=t&15;
  float g=0.f;
  for(int ch=0;ch<16;ch++)g+=g_Gpart[((b*4+h)*16+ch)*256+t];
  float nq=g_nrm[b*128+h*16+c],nk=g_nrm[b*128+64+h*16+d];
  float v=g/(nq*nk)*temp[h];
  float m=v;
  for(int o=8;o;o>>=1)m=fmaxf(m,__shfl_xor_sync(0xffffffffu,m,o,16));
  float e=expf(v-m),s2=e;
  for(int o=8;o;o>>=1)s2+=__shfl_xor_sync(0xffffffffu,s2,o,16);
  g_attn[(b*4+h)*256+c*16+d]=e/s2;
}

__global__ __launch_bounds__(256) void k_xca(const float* __restrict__ nw,const float* __restrict__ nb){
  __shared__ float vs[64][65],xc[64][65],at[1024],mu[64],rs[64];
  int b=blockIdx.x>>9,n0=(blockIdx.x&511)<<6,t=threadIdx.x;
  for(int i=0;i<16;i++){int e=t+256*i;int r=e>>6,n=e&63;
    vs[r][n]=g_qkvt[(b*192+128+r)*S+n0+n];}
  for(int i=0;i<4;i++)at[t+256*i]=g_attn[b*1024+t+256*i];
  __syncthreads();
  int sl=t&63,og=t>>6;
  for(int i=0;i<16;i++){
    float a=0.f;
    const float* ar=at+og*256+i*16;
    #pragma unroll
    for(int d=0;d<16;d++)a+=ar[d]*vs[og*16+d][sl];
    xc[og*16+i][sl]=a;
  }
  __syncthreads();
  if(t<64){
    float s1=0.f;
    for(int c2=0;c2<64;c2++)s1+=xc[c2][t];
    float m=s1*(1.f/64.f),sq=0.f;
    for(int c2=0;c2<64;c2++){float d2=xc[c2][t]-m;sq+=d2*d2;}
    mu[t]=m;rs[t]=rsqrtf(sq*(1.f/64.f)+1e-5f);
  }
  __syncthreads();
  for(int i=0;i<16;i++){int c=og*16+i;
    g_x5[(b*64+c)*S+n0+sl]=(xc[c][sl]-mu[sl])*rs[sl]*nw[c]+nb[c];}
}

template<int MODE>
__global__ __launch_bounds__(256) void k_pw(int inid,int auxid,int outid,
    const float* __restrict__ w,const float* __restrict__ bias){
  __shared__ float xs[64][65],ws2[64][65];
  const float* in=bufptr(inid);const float* aux=bufptr(auxid);float* out=bufptr(outid);
  int b=blockIdx.x>>9,s0=(blockIdx.x&511)<<6,t=threadIdx.x;
  for(int i=0;i<16;i++){int e=t+256*i;int c=e>>6,s=e&63;
    xs[c][s]=in[(b*64+c)*S+s0+s];ws2[c][s]=w[e];}
  __syncthreads();
  int sg=t&15,og=t>>4;
  float acc[4][4];
  for(int i=0;i<4;i++)for(int m=0;m<4;m++)acc[i][m]=0.f;
  for(int c=0;c<64;c++){
    float xv[4],wv[4];
    #pragma unroll
    for(int m=0;m<4;m++)xv[m]=xs[c][sg+16*m];
    #pragma unroll
    for(int i=0;i<4;i++)wv[i]=ws2[og+16*i][c];
    #pragma unroll
    for(int i=0;i<4;i++)
      #pragma unroll
      for(int m=0;m<4;m++)acc[i][m]+=wv[i]*xv[m];
  }
  for(int i=0;i<4;i++){
    int o=og+16*i;float bv=bias[o];
    for(int m=0;m<4;m++){
      int idx=(b*64+o)*S+s0+sg+16*m;
      float v=acc[i][m]+bv;
      if(MODE==1)v=0.5f*v*(1.f+erff(v*0.70710678118654752f));
      if(MODE==2)v*=aux[idx];
      if(MODE==3)v+=aux[idx];
      out[idx]=v;
    }
  }
}

__global__ __launch_bounds__(256) void k_dw5(int inid,int outid,
    const float* __restrict__ wt,const float* __restrict__ bias){
  __shared__ float pl[5][32][33];__shared__ float wsm[125];
  const float* in=bufptr(inid);float* out=bufptr(outid);
  int bc=blockIdx.x>>5,z=blockIdx.x&31,c=bc&63,t=threadIdx.x;
  if(t<125)wsm[t]=wt[c*125+t];
  const float* base=in+bc*S;
  for(int i=0;i<20;i++){int e=t+256*i;int p=e>>10,rem=e&1023;
    int zz=z+p-2;pl[p][rem>>5][rem&31]=((unsigned)zz<32u)?base[zz*1024+rem]:0.f;}
  __syncthreads();
  int x=t&31,ty=t>>5;
  for(int m=0;m<4;m++){
    int y=ty+8*m;float a=bias[c];
    for(int tz=0;tz<5;tz++)for(int qy=0;qy<5;qy++){
      int yy=y+qy-2;
      if((unsigned)yy<32u)
        #pragma unroll
        for(int qx=0;qx<5;qx++){int xx=x+qx-2;
          if((unsigned)xx<32u)a+=wsm[(tz*5+qy)*5+qx]*pl[tz][yy][xx];}
    }
    out[bc*S+z*1024+y*32+x]=a;
  }
}

__global__ __launch_bounds__(256) void k_dw7(int inid,int outid,
    const float* __restrict__ wt,const float* __restrict__ bias){
  __shared__ float pl[7][32][33];__shared__ float wsm[343];
  const float* in=bufptr(inid);float* out=bufptr(outid);
  int bc=blockIdx.x>>5,z=blockIdx.x&31,c=bc&63,t=threadIdx.x;
  for(int i=t;i<343;i+=256)wsm[i]=wt[c*343+i];
  const float* base=in+bc*S;
  for(int i=0;i<28;i++){int e=t+256*i;int p=e>>10,rem=e&1023;
    int zz=z+3*p-9;pl[p][rem>>5][rem&31]=((unsigned)zz<32u)?base[zz*1024+rem]:0.f;}
  __syncthreads();
  int x=t&31,ty=t>>5;
  for(int m=0;m<4;m++){
    int y=ty+8*m;float a=bias[c];
    for(int tz=0;tz<7;tz++)for(int qy=0;qy<7;qy++){
      int yy=y+3*qy-9;
      if((unsigned)yy<32u)
        #pragma unroll
        for(int qx=0;qx<7;qx++){int xx=x+3*qx-9;
          if((unsigned)xx<32u)a+=wsm[(tz*7+qy)*7+qx]*pl[tz][yy][xx];}
    }
    out[bc*S+z*1024+y*32+x]=a;
  }
}

// offset conv via tf32 MMA: M=64 spatial, N=96 outputs, K=27*64
__global__ __launch_bounds__(256) void k_off(const float* __restrict__ offb){
  __shared__ float rows[2][64][34];
  __shared__ float wsm[96*65];
  int blk=blockIdx.x;
  int b=blk>>9,z=(blk>>4)&31,y0=(blk&15)<<1,t=threadIdx.x;
  int w=t>>5,l=t&31;
  int mt=w>>1,nh=w&1;
  int lr=l>>2,lc=l&3;
  float acc[6][4];
  for(int j=0;j<6;j++)for(int q=0;q<4;q++)acc[j][q]=0.f;
  const float* ab=g_a2+b*64*S;
  int sA_=mt*16+lr, sB_=sA_+8;
  int r0=sA_>>5,xa=sA_&31;
  int r1=sB_>>5,xb=sB_&31;
  for(int tz=0;tz<3;tz++){
    int zz=z+tz-1;bool zok=(unsigned)zz<32u;
    for(int ty=0;ty<3;ty++){
      __syncthreads();
      for(int i=0;i<17;i++){
        int e=t+256*i;int r=e/2176,rem=e-r*2176;
        int cc=rem/34,xi=rem-cc*34;
        int yy=y0+ty-1+r,gx=xi-1;
        float v=0.f;
        if(zok&&(unsigned)yy<32u&&(unsigned)gx<32u)v=ab[cc*S+zz*1024+yy*32+gx];
        rows[r][cc][xi]=tf32r(v);
      }
      for(int tx=0;tx<3;tx++){
        int k=(tz*3+ty)*3+tx;
        __syncthreads();
        for(int i=0;i<24;i++){int e=t+256*i;
          wsm[(e>>6)*65+(e&63)]=tf32r(g_offw_t[k*6144+e]);}
        __syncthreads();
        #pragma unroll
        for(int kc=0;kc<8;kc++){
          unsigned a[4];
          int cA=kc*8+lc;
          a[0]=__float_as_uint(rows[r0][cA][xa+tx]);
          a[1]=__float_as_uint(rows[r1][cA][xb+tx]);
          a[2]=__float_as_uint(rows[r0][cA+4][xa+tx]);
          a[3]=__float_as_uint(rows[r1][cA+4][xb+tx]);
          #pragma unroll
          for(int j=0;j<6;j++){
            int o=(nh*6+j)*8+lr;
            unsigned b0=__float_as_uint(wsm[o*65+cA]);
            unsigned b1=__float_as_uint(wsm[o*65+cA+4]);
            mma8(acc[j],a,b0,b1);
          }
        }
      }
    }
  }
  int spA=z*1024+(y0+r0)*32+xa;
  int spB=z*1024+(y0+r1)*32+xb;
  #pragma unroll
  for(int j=0;j<6;j++){
    int ob=(nh*6+j)*8;
    #pragma unroll
    for(int q=0;q<2;q++){
      int o=ob+2*lc+q;
      if(o<81){
        float bv=offb[o];
        g_off[(b*81+o)*S+spA]=acc[j][q]+bv;
        g_off[(b*81+o)*S+spB]=acc[j][q+2]+bv;
      }
    }
  }
}

// deformable conv: gather + tf32 MMA (M=64 outputs, N=128 spatial, K=64 per tap)
__global__ __launch_bounds__(256) void k_dcn(const float* __restrict__ dcnb){
  extern __shared__ float dyn[];
  float* samp=dyn;              // 64*132
  float* wsm=samp+64*132;       // 64*65
  float* cw=wsm+64*65;          // 1024
  int* ci=(int*)(cw+1024);      // 1024
  int b=blockIdx.x>>8,s0=(blockIdx.x&255)<<7,t=threadIdx.x;
  int w=t>>5,l=t&31,mt=w>>1,nh=w&1,lr=l>>2,lc=l&3;
  float acc[8][4];
  for(int j=0;j<8;j++)for(int q=0;q<4;q++)acc[j][q]=0.f;
  const float* ab=g_a2+b*64*S;
  for(int k=0;k<27;k++){
    __syncthreads();
    if(t<128){
      int s=s0+t;
      int z=s>>10,y=(s>>5)&31,x=s&31;
      int kz=k/9,ky=(k/3)%3,kx=k%3;
      float pz=(float)(z+kz-1)+g_off[(b*81+3*k+0)*S+s];
      float py=(float)(y+ky-1)+g_off[(b*81+3*k+1)*S+s];
      float px=(float)(x+kx-1)+g_off[(b*81+3*k+2)*S+s];
      float fz=floorf(pz),fy=floorf(py),fx=floorf(px);
      float wz=pz-fz,wy=py-fy,wx=px-fx;
      int z0=(int)fz,y0=(int)fy,x0=(int)fx;
      #pragma unroll
      for(int cn=0;cn<8;cn++){
        int dz=cn>>2,dy=(cn>>1)&1,dx=cn&1;
        int iz=z0+dz,iy=y0+dy,ix=x0+dx;
        float wv=(dz?wz:1.f-wz)*(dy?wy:1.f-wy)*(dx?wx:1.f-wx);
        bool ok=(unsigned)iz<32u&&(unsigned)iy<32u&&(unsigned)ix<32u;
        int czi=min(max(iz,0),31),cyi=min(max(iy,0),31),cxi=min(max(ix,0),31);
        cw[cn*128+t]=ok?wv:0.f;
        ci[cn*128+t]=(czi*32+cyi)*32+cxi;
      }
    }
    for(int i=0;i<16;i++){int e=t+256*i;
      wsm[(e>>6)*65+(e&63)]=tf32r(g_dcnw_t[k*4096+e]);}
    __syncthreads();
    for(int i=0;i<32;i++){
      int e=t+256*i;int cc=e>>7,sp=e&127;
      const float* ap=ab+cc*S;
      float v=0.f;
      #pragma unroll
      for(int cn=0;cn<8;cn++)v+=cw[cn*128+sp]*ap[ci[cn*128+sp]];
      samp[cc*132+sp]=tf32r(v);
    }
    __syncthreads();
    #pragma unroll
    for(int kc=0;kc<8;kc++){
      unsigned a[4];
      int oA=mt*16+lr,cA=kc*8+lc;
      a[0]=__float_as_uint(wsm[oA*65+cA]);
      a[1]=__float_as_uint(wsm[(oA+8)*65+cA]);
      a[2]=__float_as_uint(wsm[oA*65+cA+4]);
      a[3]=__float_as_uint(wsm[(oA+8)*65+cA+4]);
      #pragma unroll
      for(int j=0;j<8;j++){
        int sp=(nh*8+j)*8+lr;
        unsigned b0=__float_as_uint(samp[cA*132+sp]);
        unsigned b1=__float_as_uint(samp[(cA+4)*132+sp]);
        mma8(acc[j],a,b0,b1);
      }
    }
  }
  int oA=mt*16+lr;
  float bv0=dcnb[oA],bv1=dcnb[oA+8];
  #pragma unroll
  for(int j=0;j<8;j++){
    int spb=(nh*8+j)*8;
    #pragma unroll
    for(int q=0;q<2;q++){
      int sp=spb+2*lc+q;
      g_dcn[(b*64+oA)*S+s0+sp]=acc[j][q]+bv0;
      g_dcn[(b*64+oA+8)*S+s0+sp]=acc[j][q+2]+bv1;
    }
  }
}

__global__ __launch_bounds__(256) void k_final(const float* __restrict__ n2w,
    const float* __restrict__ n2b,const float* __restrict__ ow,
    const float* __restrict__ ob,float* __restrict__ out){
  __shared__ float Msm[64][65],wsm[64][65],mu[64],rs[64];
  int b=blockIdx.x>>9,g=blockIdx.x&511,t=threadIdx.x;
  for(int i=0;i<16;i++){int e=t+256*i;int r=e>>6,p=e&63;
    Msm[r][p]=g_yfin[(b*64+r)*S+g+(p<<9)];
    wsm[r][p]=ow[e];}
  __syncthreads();
  if(t<64){
    float s1=0.f;
    for(int p=0;p<64;p++)s1+=Msm[t][p];
    float m=s1*(1.f/64.f),sq=0.f;
    for(int p=0;p<64;p++){float d=Msm[t][p]-m;sq+=d*d;}
    mu[t]=m;rs[t]=rsqrtf(sq*(1.f/64.f)+1e-5f);
  }
  __syncthreads();
  for(int i=0;i<16;i++){int e=t+256*i;int r=e>>6,p=e&63;
    Msm[r][p]=(Msm[r][p]-mu[r])*rs[r]*n2w[p]+n2b[p];}
  __syncthreads();
  int og=t&15,sg=t>>4;
  float acc[4][4];
  for(int m=0;m<4;m++)for(int i=0;i<4;i++)acc[m][i]=0.f;
  for(int p=0;p<64;p++){
    float xv[4],wv[4];
    #pragma unroll
    for(int m=0;m<4;m++)xv[m]=Msm[sg+16*m][p];
    #pragma unroll
    for(int i=0;i<4;i++)wv[i]=wsm[og+16*i][p];
    #pragma unroll
    for(int m=0;m<4;m++)
      #pragma unroll
      for(int i=0;i<4;i++)acc[m][i]+=xv[m]*wv[i];
  }
  for(int m=0;m<4;m++){
    int q=(g<<6)+sg+16*m;
    for(int i=0;i<4;i++){
      int o=og+16*i;
      out[(b*S+q)*64+o]=acc[m][i]+ob[o];
    }
  }
}

extern "C" void kernel_launch(void* const* d_in,const int* in_sizes,int n_in,
                              void* d_out,int out_size){
  const float* x   =(const float*)d_in[0];
  const float* temp=(const float*)d_in[1];
  const float* qkvw=(const float*)d_in[2];
  const float* nw  =(const float*)d_in[3];
  const float* nb  =(const float*)d_in[4];
  const float* p1w =(const float*)d_in[5];
  const float* p1b =(const float*)d_in[6];
  const float* c0w =(const float*)d_in[7];
  const float* c0b =(const float*)d_in[8];
  const float* cspw=(const float*)d_in[9];
  const float* cspb=(const float*)d_in[10];
  const float* offw=(const float*)d_in[11];
  const float* offb=(const float*)d_in[12];
  const float* dcnw=(const float*)d_in[13];
  const float* dcnb=(const float*)d_in[14];
  const float* c1w =(const float*)d_in[15];
  const float* c1b =(const float*)d_in[16];
  const float* p2w =(const float*)d_in[17];
  const float* p2b =(const float*)d_in[18];
  const float* n2w =(const float*)d_in[19];
  const float* n2b =(const float*)d_in[20];
  const float* ow  =(const float*)d_in[21];
  const float* ob  =(const float*)d_in[22];
  float* out=(float*)d_out;

  int dcn_smem=(64*132+64*65+1024+1024)*4;  // 58624 B
  cudaFuncSetAttribute(k_dcn,cudaFuncAttributeMaxDynamicSharedMemorySize,dcn_smem);

  k_wprep<<<648,256>>>(offw,dcnw);
  k_qkv<<<1024,256>>>(x,qkvw);
  k_sumsq<<<256,256>>>();
  k_gram<<<128,256>>>();
  k_softmax<<<8,256>>>(temp);
  k_xca<<<1024,256>>>(nw,nb);
  k_pw<1><<<1024,256>>>(0,0,1,p1w,p1b);   // u = gelu(proj1(x5))
  k_dw5<<<4096,256>>>(1,2,c0w,c0b);       // a1 = dw5(u)
  k_dw7<<<4096,256>>>(2,3,cspw,cspb);     // a2 = dw7(a1)
  k_off<<<1024,256>>>(offb);              // offsets from a2 (tf32 MMA)
  k_dcn<<<512,256,dcn_smem>>>(dcnb);      // deformable conv (tf32 MMA)
  k_pw<2><<<1024,256>>>(4,1,2,c1w,c1b);   // a1 = (conv1(dcn)+b)*u
  k_pw<3><<<1024,256>>>(2,0,5,p2w,p2b);   // yfin = proj2(a1)+x5
  k_final<<<1024,256>>>(n2w,n2b,ow,ob,out);
}

// round 13
// speedup vs baseline: 1.4087x; 1.3219x over previous
#include <cuda_runtime.h>
#include <math.h>

#define S 32768

static __device__ float g_qkvt[2*192*S];
static __device__ float g_nrm[2*128];
static __device__ float g_Gpart[2*4*16*256];
static __device__ float g_attn[2*4*256];
static __device__ float g_x5[2*64*S];
static __device__ float g_u[2*64*S];
static __device__ float g_a1[2*64*S];
static __device__ float g_a2[2*64*S];
static __device__ float g_a2t[2*64*S];        // spatial-major [b][s][c]
static __device__ float g_off[2*81*S];
static __device__ float g_dcn[2*64*S];
static __device__ float g_yfin[2*64*S];
static __device__ float g_offw_t[27*96*64];   // [tap][o pad96][c]
static __device__ float g_dcnw_t[27*64*64];   // [tap][o][c]

__device__ __forceinline__ float* bufptr(int id){
  switch(id){case 0:return g_x5;case 1:return g_u;case 2:return g_a1;
  case 3:return g_a2;case 4:return g_dcn;default:return g_yfin;}
}

__device__ __forceinline__ float tf32r(float x){
  unsigned u; asm("cvt.rna.tf32.f32 %0,%1;":"=r"(u):"f"(x));
  return __uint_as_float(u);
}

__device__ __forceinline__ void mma8(float* d,const unsigned* a,unsigned b0,unsigned b1){
  asm volatile("mma.sync.aligned.m16n8k8.row.col.f32.tf32.tf32.f32 "
    "{%0,%1,%2,%3},{%4,%5,%6,%7},{%8,%9},{%0,%1,%2,%3};"
    :"+f"(d[0]),"+f"(d[1]),"+f"(d[2]),"+f"(d[3])
    :"r"(a[0]),"r"(a[1]),"r"(a[2]),"r"(a[3]),"r"(b0),"r"(b1));
}

__global__ void k_wprep(const float* __restrict__ offw,const float* __restrict__ dcnw){
  int t=blockIdx.x*256+threadIdx.x;
  if(t<27*96*64){int k=t/(96*64);int rem=t-k*96*64;int o=rem>>6,c=rem&63;
    g_offw_t[t]=(o<81)?offw[(o*64+c)*27+k]:0.f;}
  if(t<27*64*64){int k=t>>12;int rem=t&4095;int o=rem>>6,c=rem&63;
    g_dcnw_t[t]=dcnw[(o*64+c)*27+k];}
}

__global__ __launch_bounds__(256) void k_qkv(const float* __restrict__ x,const float* __restrict__ w){
  __shared__ float xs[64][65],ws[64][65];
  int b=blockIdx.x>>9,n0=(blockIdx.x&511)<<6,t=threadIdx.x;
  const float* xp=x+(b*S+n0)*64;
  for(int i=0;i<16;i++){int e=t+256*i;xs[e>>6][e&63]=xp[e];}
  int ng=t&15,og=t>>4;
  for(int pass=0;pass<3;pass++){
    __syncthreads();
    for(int i=0;i<16;i++){int e=t+256*i;ws[e>>6][e&63]=w[pass*4096+e];}
    __syncthreads();
    float acc[4][4];
    for(int i=0;i<4;i++)for(int m=0;m<4;m++)acc[i][m]=0.f;
    for(int c=0;c<64;c++){
      float xv[4],wv[4];
      #pragma unroll
      for(int m=0;m<4;m++)xv[m]=xs[ng+16*m][c];
      #pragma unroll
      for(int i=0;i<4;i++)wv[i]=ws[og+16*i][c];
      #pragma unroll
      for(int i=0;i<4;i++)
        #pragma unroll
        for(int m=0;m<4;m++)acc[i][m]+=wv[i]*xv[m];
    }
    for(int i=0;i<4;i++){int j=pass*64+og+16*i;
      for(int m=0;m<4;m++)g_qkvt[(b*192+j)*S+n0+ng+16*m]=acc[i][m];}
  }
}

__global__ void k_sumsq(){
  int b=blockIdx.x>>7,j=blockIdx.x&127,t=threadIdx.x;
  const float* row=g_qkvt+(b*192+j)*S;
  float p=0.f;
  for(int i=0;i<128;i++){float v=row[t+256*i];p+=v*v;}
  __shared__ float red[256];
  red[t]=p;__syncthreads();
  for(int st=128;st>0;st>>=1){if(t<st)red[t]+=red[t+st];__syncthreads();}
  if(t==0)g_nrm[b*128+j]=fmaxf(sqrtf(red[0]),1e-12f);
}

__global__ __launch_bounds__(256) void k_gram(){
  __shared__ float qs[16][129],ks[16][129];
  int id=blockIdx.x,chunk=id&15,h=(id>>4)&3,b=id>>6,t=threadIdx.x;
  int c=t>>4,d=t&15,nbase=chunk*2048;
  const float* qrow=g_qkvt+(b*192+h*16)*S;
  const float* krow=g_qkvt+(b*192+64+h*16)*S;
  float acc=0.f;
  for(int ch=0;ch<16;ch++){
    int nb=nbase+ch*128;
    __syncthreads();
    for(int i=0;i<16;i++){int e=t+256*i;int r=e>>7,n=e&127;
      if(r<16)qs[r][n]=qrow[r*S+nb+n];else ks[r-16][n]=krow[(r-16)*S+nb+n];}
    __syncthreads();
    for(int n=0;n<128;n++)acc+=qs[c][n]*ks[d][n];
  }
  g_Gpart[((b*4+h)*16+chunk)*256+c*16+d]=acc;
}

__global__ void k_softmax(const float* __restrict__ temp){
  int b=blockIdx.x>>2,h=blockIdx.x&3,t=threadIdx.x;
  int c=t>>4,d=t&15;
  float g=0.f;
  for(int ch=0;ch<16;ch++)g+=g_Gpart[((b*4+h)*16+ch)*256+t];
  float nq=g_nrm[b*128+h*16+c],nk=g_nrm[b*128+64+h*16+d];
  float v=g/(nq*nk)*temp[h];
  float m=v;
  for(int o=8;o;o>>=1)m=fmaxf(m,__shfl_xor_sync(0xffffffffu,m,o,16));
  float e=expf(v-m),s2=e;
  for(int o=8;o;o>>=1)s2+=__shfl_xor_sync(0xffffffffu,s2,o,16);
  g_attn[(b*4+h)*256+c*16+d]=e/s2;
}

__global__ __launch_bounds__(256) void k_xca(const float* __restrict__ nw,const float* __restrict__ nb){
  __shared__ float vs[64][65],xc[64][65],at[1024],mu[64],rs[64];
  int b=blockIdx.x>>9,n0=(blockIdx.x&511)<<6,t=threadIdx.x;
  for(int i=0;i<16;i++){int e=t+256*i;int r=e>>6,n=e&63;
    vs[r][n]=g_qkvt[(b*192+128+r)*S+n0+n];}
  for(int i=0;i<4;i++)at[t+256*i]=g_attn[b*1024+t+256*i];
  __syncthreads();
  int sl=t&63,og=t>>6;
  for(int i=0;i<16;i++){
    float a=0.f;
    const float* ar=at+og*256+i*16;
    #pragma unroll
    for(int d=0;d<16;d++)a+=ar[d]*vs[og*16+d][sl];
    xc[og*16+i][sl]=a;
  }
  __syncthreads();
  if(t<64){
    float s1=0.f;
    for(int c2=0;c2<64;c2++)s1+=xc[c2][t];
    float m=s1*(1.f/64.f),sq=0.f;
    for(int c2=0;c2<64;c2++){float d2=xc[c2][t]-m;sq+=d2*d2;}
    mu[t]=m;rs[t]=rsqrtf(sq*(1.f/64.f)+1e-5f);
  }
  __syncthreads();
  for(int i=0;i<16;i++){int c=og*16+i;
    g_x5[(b*64+c)*S+n0+sl]=(xc[c][sl]-mu[sl])*rs[sl]*nw[c]+nb[c];}
}

template<int MODE>
__global__ __launch_bounds__(256) void k_pw(int inid,int auxid,int outid,
    const float* __restrict__ w,const float* __restrict__ bias){
  __shared__ float xs[64][65],ws2[64][65];
  const float* in=bufptr(inid);const float* aux=bufptr(auxid);float* out=bufptr(outid);
  int b=blockIdx.x>>9,s0=(blockIdx.x&511)<<6,t=threadIdx.x;
  for(int i=0;i<16;i++){int e=t+256*i;int c=e>>6,s=e&63;
    xs[c][s]=in[(b*64+c)*S+s0+s];ws2[c][s]=w[e];}
  __syncthreads();
  int sg=t&15,og=t>>4;
  float acc[4][4];
  for(int i=0;i<4;i++)for(int m=0;m<4;m++)acc[i][m]=0.f;
  for(int c=0;c<64;c++){
    float xv[4],wv[4];
    #pragma unroll
    for(int m=0;m<4;m++)xv[m]=xs[c][sg+16*m];
    #pragma unroll
    for(int i=0;i<4;i++)wv[i]=ws2[og+16*i][c];
    #pragma unroll
    for(int i=0;i<4;i++)
      #pragma unroll
      for(int m=0;m<4;m++)acc[i][m]+=wv[i]*xv[m];
  }
  for(int i=0;i<4;i++){
    int o=og+16*i;float bv=bias[o];
    for(int m=0;m<4;m++){
      int idx=(b*64+o)*S+s0+sg+16*m;
      float v=acc[i][m]+bv;
      if(MODE==1)v=0.5f*v*(1.f+erff(v*0.70710678118654752f));
      if(MODE==2)v*=aux[idx];
      if(MODE==3)v+=aux[idx];
      out[idx]=v;
    }
  }
}

__global__ __launch_bounds__(256) void k_dw5(int inid,int outid,
    const float* __restrict__ wt,const float* __restrict__ bias){
  __shared__ float pl[5][32][33];__shared__ float wsm[125];
  const float* in=bufptr(inid);float* out=bufptr(outid);
  int bc=blockIdx.x>>5,z=blockIdx.x&31,c=bc&63,t=threadIdx.x;
  if(t<125)wsm[t]=wt[c*125+t];
  const float* base=in+bc*S;
  for(int i=0;i<20;i++){int e=t+256*i;int p=e>>10,rem=e&1023;
    int zz=z+p-2;pl[p][rem>>5][rem&31]=((unsigned)zz<32u)?base[zz*1024+rem]:0.f;}
  __syncthreads();
  int x=t&31,ty=t>>5;
  float acc[4];
  float bv=bias[c];
  #pragma unroll
  for(int m=0;m<4;m++)acc[m]=bv;
  for(int tz=0;tz<5;tz++)
    for(int qy=0;qy<5;qy++){
      float w5[5];
      #pragma unroll
      for(int qx=0;qx<5;qx++)w5[qx]=wsm[(tz*5+qy)*5+qx];
      int yb=qy-2;
      #pragma unroll
      for(int qx=0;qx<5;qx++){
        int xx=x+qx-2;
        if((unsigned)xx<32u){
          float wv=w5[qx];
          #pragma unroll
          for(int m=0;m<4;m++){
            int yy=ty+8*m+yb;
            if((unsigned)yy<32u)acc[m]+=wv*pl[tz][yy][xx];
          }
        }
      }
    }
  #pragma unroll
  for(int m=0;m<4;m++)
    out[bc*S+z*1024+(ty+8*m)*32+x]=acc[m];
}

__global__ __launch_bounds__(256) void k_dw7(int inid,int outid,
    const float* __restrict__ wt,const float* __restrict__ bias){
  __shared__ float pl[7][32][33];__shared__ float wsm[343];
  const float* in=bufptr(inid);float* out=bufptr(outid);
  int bc=blockIdx.x>>5,z=blockIdx.x&31,c=bc&63,t=threadIdx.x;
  for(int i=t;i<343;i+=256)wsm[i]=wt[c*343+i];
  const float* base=in+bc*S;
  for(int i=0;i<28;i++){int e=t+256*i;int p=e>>10,rem=e&1023;
    int zz=z+3*p-9;pl[p][rem>>5][rem&31]=((unsigned)zz<32u)?base[zz*1024+rem]:0.f;}
  __syncthreads();
  int x=t&31,ty=t>>5;
  float acc[4];
  float bv=bias[c];
  #pragma unroll
  for(int m=0;m<4;m++)acc[m]=bv;
  for(int tz=0;tz<7;tz++)
    for(int qy=0;qy<7;qy++){
      float w7[7];
      #pragma unroll
      for(int qx=0;qx<7;qx++)w7[qx]=wsm[(tz*7+qy)*7+qx];
      int yb=3*qy-9;
      #pragma unroll
      for(int qx=0;qx<7;qx++){
        int xx=x+3*qx-9;
        if((unsigned)xx<32u){
          float wv=w7[qx];
          #pragma unroll
          for(int m=0;m<4;m++){
            int yy=ty+8*m+yb;
            if((unsigned)yy<32u)acc[m]+=wv*pl[tz][yy][xx];
          }
        }
      }
    }
  #pragma unroll
  for(int m=0;m<4;m++)
    out[bc*S+z*1024+(ty+8*m)*32+x]=acc[m];
}

// tile-transpose a2 [c][s] -> a2t [s][c]
__global__ __launch_bounds__(256) void k_tr(){
  __shared__ float ts[64][65];
  int b=blockIdx.x>>9,s0=(blockIdx.x&511)<<6,t=threadIdx.x;
  for(int i=0;i<16;i++){int e=t+256*i;int c=e>>6,s=e&63;
    ts[c][s]=g_a2[(b*64+c)*S+s0+s];}
  __syncthreads();
  for(int i=0;i<16;i++){int e=t+256*i;int s=e>>6,c=e&63;
    g_a2t[(b*S+s0+s)*64+c]=ts[c][s];}
}

// offset conv via tf32 MMA: M=64 spatial, N=96 outputs, K=27*64
__global__ __launch_bounds__(256) void k_off(const float* __restrict__ offb){
  __shared__ float rows[2][64][34];
  __shared__ float wsm[96*65];
  int blk=blockIdx.x;
  int b=blk>>9,z=(blk>>4)&31,y0=(blk&15)<<1,t=threadIdx.x;
  int w=t>>5,l=t&31;
  int mt=w>>1,nh=w&1;
  int lr=l>>2,lc=l&3;
  float acc[6][4];
  for(int j=0;j<6;j++)for(int q=0;q<4;q++)acc[j][q]=0.f;
  const float* ab=g_a2+b*64*S;
  int sA_=mt*16+lr, sB_=sA_+8;
  int r0=sA_>>5,xa=sA_&31;
  int r1=sB_>>5,xb=sB_&31;
  for(int tz=0;tz<3;tz++){
    int zz=z+tz-1;bool zok=(unsigned)zz<32u;
    for(int ty=0;ty<3;ty++){
      __syncthreads();
      for(int i=0;i<17;i++){
        int e=t+256*i;int r=e/2176,rem=e-r*2176;
        int cc=rem/34,xi=rem-cc*34;
        int yy=y0+ty-1+r,gx=xi-1;
        float v=0.f;
        if(zok&&(unsigned)yy<32u&&(unsigned)gx<32u)v=ab[cc*S+zz*1024+yy*32+gx];
        rows[r][cc][xi]=tf32r(v);
      }
      for(int tx=0;tx<3;tx++){
        int k=(tz*3+ty)*3+tx;
        __syncthreads();
        for(int i=0;i<24;i++){int e=t+256*i;
          wsm[(e>>6)*65+(e&63)]=tf32r(g_offw_t[k*6144+e]);}
        __syncthreads();
        #pragma unroll
        for(int kc=0;kc<8;kc++){
          unsigned a[4];
          int cA=kc*8+lc;
          a[0]=__float_as_uint(rows[r0][cA][xa+tx]);
          a[1]=__float_as_uint(rows[r1][cA][xb+tx]);
          a[2]=__float_as_uint(rows[r0][cA+4][xa+tx]);
          a[3]=__float_as_uint(rows[r1][cA+4][xb+tx]);
          #pragma unroll
          for(int j=0;j<6;j++){
            int o=(nh*6+j)*8+lr;
            unsigned b0=__float_as_uint(wsm[o*65+cA]);
            unsigned b1=__float_as_uint(wsm[o*65+cA+4]);
            mma8(acc[j],a,b0,b1);
          }
        }
      }
    }
  }
  int spA=z*1024+(y0+r0)*32+xa;
  int spB=z*1024+(y0+r1)*32+xb;
  #pragma unroll
  for(int j=0;j<6;j++){
    int ob=(nh*6+j)*8;
    #pragma unroll
    for(int q=0;q<2;q++){
      int o=ob+2*lc+q;
      if(o<81){
        float bv=offb[o];
        g_off[(b*81+o)*S+spA]=acc[j][q]+bv;
        g_off[(b*81+o)*S+spB]=acc[j][q+2]+bv;
      }
    }
  }
}

// deformable conv: vectorized channel gather (a2t) + tf32 MMA
__global__ __launch_bounds__(256) void k_dcn(const float* __restrict__ dcnb){
  extern __shared__ float dyn[];
  float* samp=dyn;              // 128*68 (spatial-major, [sp][cc])
  float* wsm=samp+128*68;       // 64*65
  float* cw=wsm+64*65;          // 8*128
  int* ci=(int*)(cw+1024);      // 8*128
  int b=blockIdx.x>>8,s0=(blockIdx.x&255)<<7,t=threadIdx.x;
  int w=t>>5,l=t&31,mt=w>>1,nh=w&1,lr=l>>2,lc=l&3;
  float acc[8][4];
  for(int j=0;j<8;j++)for(int q=0;q<4;q++)acc[j][q]=0.f;
  const float* at=g_a2t+(size_t)b*64*S;
  for(int k=0;k<27;k++){
    __syncthreads();
    if(t<128){
      int s=s0+t;
      int z=s>>10,y=(s>>5)&31,x=s&31;
      int kz=k/9,ky=(k/3)%3,kx=k%3;
      float pz=(float)(z+kz-1)+g_off[(b*81+3*k+0)*S+s];
      float py=(float)(y+ky-1)+g_off[(b*81+3*k+1)*S+s];
      float px=(float)(x+kx-1)+g_off[(b*81+3*k+2)*S+s];
      float fz=floorf(pz),fy=floorf(py),fx=floorf(px);
      float wz=pz-fz,wy=py-fy,wx=px-fx;
      int z0=(int)fz,y0=(int)fy,x0=(int)fx;
      #pragma unroll
      for(int cn=0;cn<8;cn++){
        int dz=cn>>2,dy=(cn>>1)&1,dx=cn&1;
        int iz=z0+dz,iy=y0+dy,ix=x0+dx;
        float wv=(dz?wz:1.f-wz)*(dy?wy:1.f-wy)*(dx?wx:1.f-wx);
        bool ok=(unsigned)iz<32u&&(unsigned)iy<32u&&(unsigned)ix<32u;
        int czi=min(max(iz,0),31),cyi=min(max(iy,0),31),cxi=min(max(ix,0),31);
        cw[cn*128+t]=ok?wv:0.f;
        ci[cn*128+t]=(czi*32+cyi)*32+cxi;
      }
    }
    for(int i=0;i<16;i++){int e=t+256*i;
      wsm[(e>>6)*65+(e&63)]=tf32r(g_dcnw_t[k*4096+e]);}
    __syncthreads();
    // gather: each task = (sp, 4-channel group), float4 loads of a2t rows
    #pragma unroll
    for(int i=0;i<8;i++){
      int e=t+256*i;int sp=e>>4,q=(e&15)<<2;
      float ax=0.f,ay=0.f,az=0.f,aw=0.f;
      #pragma unroll
      for(int cn=0;cn<8;cn++){
        float wv=cw[cn*128+sp];
        const float4 v4=*(const float4*)(at+(size_t)ci[cn*128+sp]*64+q);
        ax+=wv*v4.x;ay+=wv*v4.y;az+=wv*v4.z;aw+=wv*v4.w;
      }
      float4 o4;o4.x=tf32r(ax);o4.y=tf32r(ay);o4.z=tf32r(az);o4.w=tf32r(aw);
      *(float4*)(samp+sp*68+q)=o4;
    }
    __syncthreads();
    #pragma unroll
    for(int kc=0;kc<8;kc++){
      unsigned a[4];
      int oA=mt*16+lr,cA=kc*8+lc;
      a[0]=__float_as_uint(wsm[oA*65+cA]);
      a[1]=__float_as_uint(wsm[(oA+8)*65+cA]);
      a[2]=__float_as_uint(wsm[oA*65+cA+4]);
      a[3]=__float_as_uint(wsm[(oA+8)*65+cA+4]);
      #pragma unroll
      for(int j=0;j<8;j++){
        int sp=(nh*8+j)*8+lr;
        unsigned b0=__float_as_uint(samp[sp*68+cA]);
        unsigned b1=__float_as_uint(samp[sp*68+cA+4]);
        mma8(acc[j],a,b0,b1);
      }
    }
  }
  int oA=mt*16+lr;
  float bv0=dcnb[oA],bv1=dcnb[oA+8];
  #pragma unroll
  for(int j=0;j<8;j++){
    int spb=(nh*8+j)*8;
    #pragma unroll
    for(int q=0;q<2;q++){
      int sp=spb+2*lc+q;
      g_dcn[(b*64+oA)*S+s0+sp]=acc[j][q]+bv0;
      g_dcn[(b*64+oA+8)*S+s0+sp]=acc[j][q+2]+bv1;
    }
  }
}

__global__ __launch_bounds__(256) void k_final(const float* __restrict__ n2w,
    const float* __restrict__ n2b,const float* __restrict__ ow,
    const float* __restrict__ ob,float* __restrict__ out){
  __shared__ float Msm[64][65],wsm[64][65],mu[64],rs[64];
  int b=blockIdx.x>>9,g=blockIdx.x&511,t=threadIdx.x;
  for(int i=0;i<16;i++){int e=t+256*i;int r=e>>6,p=e&63;
    Msm[r][p]=g_yfin[(b*64+r)*S+g+(p<<9)];
    wsm[r][p]=ow[e];}
  __syncthreads();
  if(t<64){
    float s1=0.f;
    for(int p=0;p<64;p++)s1+=Msm[t][p];
    float m=s1*(1.f/64.f),sq=0.f;
    for(int p=0;p<64;p++){float d=Msm[t][p]-m;sq+=d*d;}
    mu[t]=m;rs[t]=rsqrtf(sq*(1.f/64.f)+1e-5f);
  }
  __syncthreads();
  for(int i=0;i<16;i++){int e=t+256*i;int r=e>>6,p=e&63;
    Msm[r][p]=(Msm[r][p]-mu[r])*rs[r]*n2w[p]+n2b[p];}
  __syncthreads();
  int og=t&15,sg=t>>4;
  float acc[4][4];
  for(int m=0;m<4;m++)for(int i=0;i<4;i++)acc[m][i]=0.f;
  for(int p=0;p<64;p++){
    float xv[4],wv[4];
    #pragma unroll
    for(int m=0;m<4;m++)xv[m]=Msm[sg+16*m][p];
    #pragma unroll
    for(int i=0;i<4;i++)wv[i]=wsm[og+16*i][p];
    #pragma unroll
    for(int m=0;m<4;m++)
      #pragma unroll
      for(int i=0;i<4;i++)acc[m][i]+=xv[m]*wv[i];
  }
  for(int m=0;m<4;m++){
    int q=(g<<6)+sg+16*m;
    for(int i=0;i<4;i++){
      int o=og+16*i;
      out[(b*S+q)*64+o]=acc[m][i]+ob[o];
    }
  }
}

extern "C" void kernel_launch(void* const* d_in,const int* in_sizes,int n_in,
                              void* d_out,int out_size){
  const float* x   =(const float*)d_in[0];
  const float* temp=(const float*)d_in[1];
  const float* qkvw=(const float*)d_in[2];
  const float* nw  =(const float*)d_in[3];
  const float* nb  =(const float*)d_in[4];
  const float* p1w =(const float*)d_in[5];
  const float* p1b =(const float*)d_in[6];
  const float* c0w =(const float*)d_in[7];
  const float* c0b =(const float*)d_in[8];
  const float* cspw=(const float*)d_in[9];
  const float* cspb=(const float*)d_in[10];
  const float* offw=(const float*)d_in[11];
  const float* offb=(const float*)d_in[12];
  const float* dcnw=(const float*)d_in[13];
  const float* dcnb=(const float*)d_in[14];
  const float* c1w =(const float*)d_in[15];
  const float* c1b =(const float*)d_in[16];
  const float* p2w =(const float*)d_in[17];
  const float* p2b =(const float*)d_in[18];
  const float* n2w =(const float*)d_in[19];
  const float* n2b =(const float*)d_in[20];
  const float* ow  =(const float*)d_in[21];
  const float* ob  =(const float*)d_in[22];
  float* out=(float*)d_out;

  int dcn_smem=(128*68+64*65+1024+1024)*4;  // 59648 B
  cudaFuncSetAttribute(k_dcn,cudaFuncAttributeMaxDynamicSharedMemorySize,dcn_smem);

  k_wprep<<<648,256>>>(offw,dcnw);
  k_qkv<<<1024,256>>>(x,qkvw);
  k_sumsq<<<256,256>>>();
  k_gram<<<128,256>>>();
  k_softmax<<<8,256>>>(temp);
  k_xca<<<1024,256>>>(nw,nb);
  k_pw<1><<<1024,256>>>(0,0,1,p1w,p1b);   // u = gelu(proj1(x5))
  k_dw5<<<4096,256>>>(1,2,c0w,c0b);       // a1 = dw5(u)
  k_dw7<<<4096,256>>>(2,3,cspw,cspb);     // a2 = dw7(a1)
  k_tr<<<1024,256>>>();                   // a2 -> a2t (spatial-major)
  k_off<<<1024,256>>>(offb);              // offsets from a2 (tf32 MMA)
  k_dcn<<<512,256,dcn_smem>>>(dcnb);      // deformable conv (vector gather + MMA)
  k_pw<2><<<1024,256>>>(4,1,2,c1w,c1b);   // a1 = (conv1(dcn)+b)*u
  k_pw<3><<<1024,256>>>(2,0,5,p2w,p2b);   // yfin = proj2(a1)+x5
  k_final<<<1024,256>>>(n2w,n2b,ow,ob,out);
}